// round 1
// baseline (speedup 1.0000x reference)
#include <cuda_runtime.h>
#include <cuda_bf16.h>
#include <cstddef>
#include <cstdint>

// ============================================================================
// ClassicalAttentionLayer: out = softmax((x Wq^T)(x Wk^T)^T / N) (x Wv^T)
// N = 8192, D_IN = D_OUT = 1024, all fp32.
//
// Round 1: all-fp32 baseline using packed f32x2 FMAs (Blackwell FFMA2 path).
// Scratch lives in __device__ globals (no allocations allowed).
// ============================================================================

#define NROWS 8192
#define DIN   1024
#define DOUT  1024

// Scratch buffers (static device globals -- allocation-free).
__device__ float g_q[(size_t)NROWS * DOUT];
__device__ float g_k[(size_t)NROWS * DOUT];
__device__ float g_v[(size_t)NROWS * DOUT];
__device__ float g_scores[(size_t)NROWS * NROWS];

// ---------------------------------------------------------------------------
// Packed f32x2 helpers (SASS: FFMA2 -- 2x fp32 FMA throughput on sm_103a)
// ---------------------------------------------------------------------------
__device__ __forceinline__ void fma2(unsigned long long& c,
                                     unsigned long long a,
                                     unsigned long long b) {
    asm("fma.rn.f32x2 %0, %1, %2, %0;" : "+l"(c) : "l"(a), "l"(b));
}
__device__ __forceinline__ unsigned long long pack2(float lo, float hi) {
    unsigned long long r;
    asm("mov.b64 %0, {%1, %2};" : "=l"(r) : "f"(lo), "f"(hi));
    return r;
}
__device__ __forceinline__ float2 unpack2(unsigned long long v) {
    float2 r;
    asm("mov.b64 {%0, %1}, %2;" : "=f"(r.x), "=f"(r.y) : "l"(v));
    return r;
}

// ---------------------------------------------------------------------------
// Tiled GEMM.
//   TRANS_B = true : C[M,N] = alpha * A[M,K] * B[N,K]^T   (both K-contiguous)
//   TRANS_B = false: C[M,N] = alpha * A[M,K] * B[K,N]
// BM=BN=128, BK=16, 256 threads, 8x8 per-thread microtile (f32x2 packed).
// Requires M%128==0, N%128==0, K%16==0 (holds for all 5 GEMMs here).
// ---------------------------------------------------------------------------
#define BM 128
#define BN 128
#define BK 16
#define SPAD 4   // smem row = 132 floats: 16B-aligned rows, de-conflicts stores

template <bool TRANS_B>
__global__ __launch_bounds__(256)
void gemm_kernel(const float* __restrict__ A, const float* __restrict__ B,
                 float* __restrict__ C, int M, int N, int K, float alpha)
{
    __shared__ float As[BK][BM + SPAD];
    __shared__ float Bs[BK][BN + SPAD];

    const int tid = threadIdx.x;
    const int tx  = tid & 15;   // 0..15 -> output cols tx*8..tx*8+7
    const int ty  = tid >> 4;   // 0..15 -> output rows ty*8..ty*8+7
    const int rowA = blockIdx.y * BM;
    const int colB = blockIdx.x * BN;

    // transpose-load lane mapping (A always; B in NT mode)
    const int lr = tid >> 2;          // 0..63
    const int lc = (tid & 3) * 4;     // 0,4,8,12
    // direct-load lane mapping (B in NN mode)
    const int br = tid >> 5;          // 0..7
    const int bc = (tid & 31) * 4;    // 0..124

    unsigned long long acc[8][4];
    #pragma unroll
    for (int i = 0; i < 8; i++)
        #pragma unroll
        for (int j = 0; j < 4; j++)
            acc[i][j] = 0ULL;   // packed (0.0f, 0.0f)

    for (int k0 = 0; k0 < K; k0 += BK) {
        // ---- stage global -> regs ----
        float4 a0 = *(const float4*)(A + (size_t)(rowA + lr)      * K + k0 + lc);
        float4 a1 = *(const float4*)(A + (size_t)(rowA + lr + 64) * K + k0 + lc);
        float4 b0, b1;
        if (TRANS_B) {
            b0 = *(const float4*)(B + (size_t)(colB + lr)      * K + k0 + lc);
            b1 = *(const float4*)(B + (size_t)(colB + lr + 64) * K + k0 + lc);
        } else {
            b0 = *(const float4*)(B + (size_t)(k0 + br)     * N + colB + bc);
            b1 = *(const float4*)(B + (size_t)(k0 + br + 8) * N + colB + bc);
        }

        __syncthreads();   // previous iteration finished reading smem

        // ---- regs -> smem ----
        As[lc + 0][lr] = a0.x; As[lc + 1][lr] = a0.y;
        As[lc + 2][lr] = a0.z; As[lc + 3][lr] = a0.w;
        As[lc + 0][lr + 64] = a1.x; As[lc + 1][lr + 64] = a1.y;
        As[lc + 2][lr + 64] = a1.z; As[lc + 3][lr + 64] = a1.w;
        if (TRANS_B) {
            Bs[lc + 0][lr] = b0.x; Bs[lc + 1][lr] = b0.y;
            Bs[lc + 2][lr] = b0.z; Bs[lc + 3][lr] = b0.w;
            Bs[lc + 0][lr + 64] = b1.x; Bs[lc + 1][lr + 64] = b1.y;
            Bs[lc + 2][lr + 64] = b1.z; Bs[lc + 3][lr + 64] = b1.w;
        } else {
            *(float4*)&Bs[br][bc]     = b0;
            *(float4*)&Bs[br + 8][bc] = b1;
        }

        __syncthreads();

        // ---- compute ----
        #pragma unroll
        for (int kk = 0; kk < BK; kk++) {
            float4 av0 = *(const float4*)&As[kk][ty * 8];
            float4 av1 = *(const float4*)&As[kk][ty * 8 + 4];
            float4 bv0 = *(const float4*)&Bs[kk][tx * 8];
            float4 bv1 = *(const float4*)&Bs[kk][tx * 8 + 4];

            unsigned long long bp[4];
            bp[0] = pack2(bv0.x, bv0.y);
            bp[1] = pack2(bv0.z, bv0.w);
            bp[2] = pack2(bv1.x, bv1.y);
            bp[3] = pack2(bv1.z, bv1.w);

            float a8[8] = {av0.x, av0.y, av0.z, av0.w,
                           av1.x, av1.y, av1.z, av1.w};
            #pragma unroll
            for (int i = 0; i < 8; i++) {
                unsigned long long ad = pack2(a8[i], a8[i]);
                fma2(acc[i][0], ad, bp[0]);
                fma2(acc[i][1], ad, bp[1]);
                fma2(acc[i][2], ad, bp[2]);
                fma2(acc[i][3], ad, bp[3]);
            }
        }
    }

    // ---- store ----
    #pragma unroll
    for (int i = 0; i < 8; i++) {
        const size_t row = (size_t)(rowA + ty * 8 + i);
        float2 u0 = unpack2(acc[i][0]);
        float2 u1 = unpack2(acc[i][1]);
        float2 u2 = unpack2(acc[i][2]);
        float2 u3 = unpack2(acc[i][3]);
        float4 o0 = make_float4(u0.x * alpha, u0.y * alpha, u1.x * alpha, u1.y * alpha);
        float4 o1 = make_float4(u2.x * alpha, u2.y * alpha, u3.x * alpha, u3.y * alpha);
        *(float4*)(C + row * N + colB + tx * 8)     = o0;
        *(float4*)(C + row * N + colB + tx * 8 + 4) = o1;
    }
}

// ---------------------------------------------------------------------------
// Row softmax over n columns, in place. One block per row, 256 threads.
// ---------------------------------------------------------------------------
__global__ __launch_bounds__(256)
void softmax_rows(float* __restrict__ S, int n)
{
    __shared__ float red[256];
    const int tid = threadIdx.x;
    float* p = S + (size_t)blockIdx.x * n;

    // max
    float m = -3.402823466e+38f;
    for (int j = tid; j < n; j += 256) m = fmaxf(m, p[j]);
    red[tid] = m;
    __syncthreads();
    for (int s = 128; s > 0; s >>= 1) {
        if (tid < s) red[tid] = fmaxf(red[tid], red[tid + s]);
        __syncthreads();
    }
    m = red[0];
    __syncthreads();

    // exp + sum
    float sum = 0.0f;
    for (int j = tid; j < n; j += 256) {
        float e = expf(p[j] - m);
        p[j] = e;
        sum += e;
    }
    red[tid] = sum;
    __syncthreads();
    for (int s = 128; s > 0; s >>= 1) {
        if (tid < s) red[tid] += red[tid + s];
        __syncthreads();
    }
    const float inv = 1.0f / red[0];

    // normalize
    for (int j = tid; j < n; j += 256) p[j] *= inv;
}

// ---------------------------------------------------------------------------
// Launch
// ---------------------------------------------------------------------------
extern "C" void kernel_launch(void* const* d_in, const int* in_sizes, int n_in,
                              void* d_out, int out_size)
{
    const float* x  = (const float*)d_in[0];
    const float* Wq = (const float*)d_in[1];
    const float* Wk = (const float*)d_in[2];
    const float* Wv = (const float*)d_in[3];
    float* out = (float*)d_out;

    float *q, *k, *v, *sc;
    cudaGetSymbolAddress((void**)&q,  g_q);
    cudaGetSymbolAddress((void**)&k,  g_k);
    cudaGetSymbolAddress((void**)&v,  g_v);
    cudaGetSymbolAddress((void**)&sc, g_scores);

    const dim3 blk(256);

    // QKV projections: [8192,1024] = x @ W^T   (NT)
    {
        dim3 grid(DOUT / BN, NROWS / BM);
        gemm_kernel<true><<<grid, blk>>>(x, Wq, q, NROWS, DOUT, DIN, 1.0f);
        gemm_kernel<true><<<grid, blk>>>(x, Wk, k, NROWS, DOUT, DIN, 1.0f);
        gemm_kernel<true><<<grid, blk>>>(x, Wv, v, NROWS, DOUT, DIN, 1.0f);
    }

    // scores = (q @ k^T) / NROWS   (NT)
    {
        dim3 grid(NROWS / BN, NROWS / BM);
        gemm_kernel<true><<<grid, blk>>>(q, k, sc, NROWS, NROWS, DOUT,
                                         1.0f / (float)NROWS);
    }

    // softmax over rows
    softmax_rows<<<NROWS, blk>>>(sc, NROWS);

    // out = attn @ v   (NN)
    {
        dim3 grid(DOUT / BN, NROWS / BM);
        gemm_kernel<false><<<grid, blk>>>(sc, v, out, NROWS, DOUT, NROWS, 1.0f);
    }
}

// round 3
// speedup vs baseline: 2.4260x; 2.4260x over previous
#include <cuda_runtime.h>
#include <cuda_bf16.h>
#include <cstdint>
#include <cstddef>

// ============================================================================
// ClassicalAttentionLayer on GB300, round 3.
// Build config targets baseline sm_103 (no 'a'): tcgen05 unavailable.
// => warp-level mma.sync bf16 (split hi/lo, fp32 accum) tensor-core GEMMs.
//
//   q  = NT(x, Wq)            [8192,1024]
//   k  = NT(x, Wk)            [8192,1024]
//   vT = NT(Wv, x)            [1024,8192]
//   sc = NT(q, k) / 8192      [8192,8192]
//   softmax rows (smem-resident)
//   out= NT(sc, vT)           [8192,1024]
// ============================================================================

#define NROWS 8192
#define DMODEL 1024

__device__ float g_q[(size_t)NROWS * DMODEL];
__device__ float g_k[(size_t)NROWS * DMODEL];
__device__ float g_vt[(size_t)DMODEL * NROWS];
__device__ float g_scores[(size_t)NROWS * NROWS];

// ---------------------------------------------------------------------------
// PTX helpers (all baseline sm_80/sm_90 features -- compile for compute_103)
// ---------------------------------------------------------------------------
__device__ __forceinline__ uint32_t smem_u32(const void* p) {
    uint32_t a;
    asm("{ .reg .u64 t; cvta.to.shared.u64 t, %1; cvt.u32.u64 %0, t; }"
        : "=r"(a) : "l"(p));
    return a;
}

__device__ __forceinline__ void ldsm4(uint32_t* r, uint32_t addr) {
    asm volatile("ldmatrix.sync.aligned.m8n8.x4.shared.b16 {%0,%1,%2,%3}, [%4];"
                 : "=r"(r[0]), "=r"(r[1]), "=r"(r[2]), "=r"(r[3]) : "r"(addr));
}

__device__ __forceinline__ void mma_bf16(float* d, const uint32_t* a,
                                         const uint32_t* b) {
    asm volatile(
        "mma.sync.aligned.m16n8k16.row.col.f32.bf16.bf16.f32 "
        "{%0,%1,%2,%3}, {%4,%5,%6,%7}, {%8,%9}, {%0,%1,%2,%3};"
        : "+f"(d[0]), "+f"(d[1]), "+f"(d[2]), "+f"(d[3])
        : "r"(a[0]), "r"(a[1]), "r"(a[2]), "r"(a[3]), "r"(b[0]), "r"(b[1]));
}

// fp32 -> (bf16 hi, bf16 lo) split, 4 elems. hi = RN-bf16(x), lo = RN-bf16(x-hi).
__device__ __forceinline__ void split4(float4 f, uint2& hi, uint2& lo) {
    uint32_t u0 = __float_as_uint(f.x), u1 = __float_as_uint(f.y);
    uint32_t u2 = __float_as_uint(f.z), u3 = __float_as_uint(f.w);
    uint32_t r0 = u0 + 0x7FFFu + ((u0 >> 16) & 1u);
    uint32_t r1 = u1 + 0x7FFFu + ((u1 >> 16) & 1u);
    uint32_t r2 = u2 + 0x7FFFu + ((u2 >> 16) & 1u);
    uint32_t r3 = u3 + 0x7FFFu + ((u3 >> 16) & 1u);
    hi.x = __byte_perm(r0, r1, 0x7632);
    hi.y = __byte_perm(r2, r3, 0x7632);
    float h0 = __uint_as_float(r0 & 0xFFFF0000u);
    float h1 = __uint_as_float(r1 & 0xFFFF0000u);
    float h2 = __uint_as_float(r2 & 0xFFFF0000u);
    float h3 = __uint_as_float(r3 & 0xFFFF0000u);
    float l0 = f.x - h0, l1 = f.y - h1, l2 = f.z - h2, l3 = f.w - h3;
    asm("cvt.rn.bf16x2.f32 %0, %1, %2;" : "=r"(lo.x) : "f"(l1), "f"(l0));
    asm("cvt.rn.bf16x2.f32 %0, %1, %2;" : "=r"(lo.y) : "f"(l3), "f"(l2));
}

__device__ __forceinline__ void sts64(uint32_t addr, uint2 v) {
    asm volatile("st.shared.v2.u32 [%0], {%1, %2};"
                 :: "r"(addr), "r"(v.x), "r"(v.y) : "memory");
}

// ---------------------------------------------------------------------------
// Split-bf16 NT GEMM: C[M,N] = alpha * A[M,K] * B[N,K]^T  (fp32 in/out)
// CTA tile 128x128, K-chunk 32 fp32, 8 warps (2x4), warp tile 64x32.
// SMEM: double-buffered Ahi/Alo/Bhi/Blo, bf16 rows padded to 40 elems (80 B)
// => conflict-free ldmatrix. Requires M%128==0, N%128==0, K%32==0.
// ---------------------------------------------------------------------------
#define BKF 32
#define KS_BYTES 80                         // padded bf16 row stride
#define TILE_BYTES (128 * KS_BYTES)         // 10240 per matrix
#define BUF_BYTES (4 * TILE_BYTES)          // Ahi,Alo,Bhi,Blo = 40960
#define SMEM_TOTAL (2 * BUF_BYTES)          // 81920

__global__ __launch_bounds__(256, 1)
void gemm_nt_split(const float* __restrict__ A, const float* __restrict__ B,
                   float* __restrict__ C, int M, int N, int K, float alpha)
{
    extern __shared__ char smem[];
    const uint32_t sb = smem_u32(smem);

    const int tid  = threadIdx.x;
    const int lane = tid & 31;
    const int wid  = tid >> 5;
    const int wm   = wid >> 2;    // 0..1 -> M offset wm*64
    const int wn   = wid & 3;     // 0..3 -> N offset wn*32

    const int m0 = blockIdx.y * 128;
    const int n0 = blockIdx.x * 128;

    // staging: each thread loads float4 at (srow + 32i, scol) for i=0..3
    const int srow = tid >> 3;          // 0..31
    const int scol = (tid & 7) * 4;     // fp32 col 0..28
    const float* Ap = A + (size_t)(m0 + srow) * K + scol;
    const float* Bp = B + (size_t)(n0 + srow) * K + scol;
    const uint32_t stoff = (uint32_t)(srow * KS_BYTES + scol * 2);

    float acc[4][4][4];
    #pragma unroll
    for (int i = 0; i < 4; i++)
        #pragma unroll
        for (int j = 0; j < 4; j++)
            #pragma unroll
            for (int t = 0; t < 4; t++) acc[i][j][t] = 0.0f;

    const int nch = K / BKF;

    float4 fa[4], fb[4];
    // preload chunk 0
    #pragma unroll
    for (int i = 0; i < 4; i++) {
        fa[i] = *(const float4*)(Ap + (size_t)(32 * i) * K);
        fb[i] = *(const float4*)(Bp + (size_t)(32 * i) * K);
    }
    // convert + store chunk 0 into buffer 0
    {
        const uint32_t aHi = sb, aLo = sb + TILE_BYTES;
        const uint32_t bHi = sb + 2 * TILE_BYTES, bLo = sb + 3 * TILE_BYTES;
        #pragma unroll
        for (int i = 0; i < 4; i++) {
            uint2 hi, lo;
            uint32_t off = stoff + (uint32_t)(32 * i * KS_BYTES);
            split4(fa[i], hi, lo);
            sts64(aHi + off, hi); sts64(aLo + off, lo);
            split4(fb[i], hi, lo);
            sts64(bHi + off, hi); sts64(bLo + off, lo);
        }
    }
    __syncthreads();

    // ldmatrix lane addressing (within a tile)
    const uint32_t a_lane_off =
        (uint32_t)((wm * 64 + (lane & 15)) * KS_BYTES + ((lane >> 4) & 1) * 16);
    const uint32_t b_lane_off =
        (uint32_t)((wn * 32 + ((lane >> 4) & 1) * 8 + (lane & 7)) * KS_BYTES
                   + ((lane >> 3) & 1) * 16);

    for (int c = 0; c < nch; c++) {
        const int b = c & 1;
        const bool more = (c + 1) < nch;

        // issue gmem loads for next chunk (overlap with MMA below)
        if (more) {
            const float* Ap2 = Ap + (size_t)(c + 1) * BKF;
            const float* Bp2 = Bp + (size_t)(c + 1) * BKF;
            #pragma unroll
            for (int i = 0; i < 4; i++) {
                fa[i] = *(const float4*)(Ap2 + (size_t)(32 * i) * K);
                fb[i] = *(const float4*)(Bp2 + (size_t)(32 * i) * K);
            }
        }

        // ---- compute on buffer b ----
        const uint32_t base = sb + (uint32_t)b * BUF_BYTES;
        const uint32_t aHi = base, aLo = base + TILE_BYTES;
        const uint32_t bHi = base + 2 * TILE_BYTES, bLo = base + 3 * TILE_BYTES;

        #pragma unroll
        for (int s = 0; s < 2; s++) {
            const uint32_t koff = (uint32_t)(s * 32);
            uint32_t ah[4][4], al[4][4], bh[2][4], bl[2][4];
            #pragma unroll
            for (int mt = 0; mt < 4; mt++) {
                ldsm4(ah[mt], aHi + a_lane_off + koff + (uint32_t)(mt * 16 * KS_BYTES));
                ldsm4(al[mt], aLo + a_lane_off + koff + (uint32_t)(mt * 16 * KS_BYTES));
            }
            #pragma unroll
            for (int np = 0; np < 2; np++) {
                ldsm4(bh[np], bHi + b_lane_off + koff + (uint32_t)(np * 16 * KS_BYTES));
                ldsm4(bl[np], bLo + b_lane_off + koff + (uint32_t)(np * 16 * KS_BYTES));
            }
            #pragma unroll
            for (int mt = 0; mt < 4; mt++) {
                #pragma unroll
                for (int nt = 0; nt < 4; nt++) {
                    const uint32_t* bhf = &bh[nt >> 1][(nt & 1) * 2];
                    const uint32_t* blf = &bl[nt >> 1][(nt & 1) * 2];
                    mma_bf16(acc[mt][nt], ah[mt], bhf);   // hi*hi
                    mma_bf16(acc[mt][nt], ah[mt], blf);   // hi*lo
                    mma_bf16(acc[mt][nt], al[mt], bhf);   // lo*hi
                }
            }
        }

        // ---- convert + store next chunk into buffer b^1 ----
        if (more) {
            const uint32_t nb = sb + (uint32_t)(b ^ 1) * BUF_BYTES;
            const uint32_t naHi = nb, naLo = nb + TILE_BYTES;
            const uint32_t nbHi = nb + 2 * TILE_BYTES, nbLo = nb + 3 * TILE_BYTES;
            #pragma unroll
            for (int i = 0; i < 4; i++) {
                uint2 hi, lo;
                uint32_t off = stoff + (uint32_t)(32 * i * KS_BYTES);
                split4(fa[i], hi, lo);
                sts64(naHi + off, hi); sts64(naLo + off, lo);
                split4(fb[i], hi, lo);
                sts64(nbHi + off, hi); sts64(nbLo + off, lo);
            }
        }
        __syncthreads();
    }

    // ---- epilogue: acc -> C (fragment layout of m16n8 C) ----
    #pragma unroll
    for (int mt = 0; mt < 4; mt++) {
        #pragma unroll
        for (int nt = 0; nt < 4; nt++) {
            const int r0  = m0 + wm * 64 + mt * 16 + (lane >> 2);
            const int col = n0 + wn * 32 + nt * 8 + (lane & 3) * 2;
            float2 v0 = make_float2(acc[mt][nt][0] * alpha, acc[mt][nt][1] * alpha);
            float2 v1 = make_float2(acc[mt][nt][2] * alpha, acc[mt][nt][3] * alpha);
            *(float2*)(C + (size_t)r0 * N + col)       = v0;
            *(float2*)(C + (size_t)(r0 + 8) * N + col) = v1;
        }
    }
}

// ---------------------------------------------------------------------------
// Row softmax over 8192 cols, smem-resident (1 gmem read + 1 gmem write).
// ---------------------------------------------------------------------------
__global__ __launch_bounds__(256)
void softmax_rows(float* __restrict__ S)
{
    __shared__ float row[8192];
    __shared__ float red[256];
    const int tid = threadIdx.x;
    float* p = S + (size_t)blockIdx.x * 8192;

    float m = -3.402823466e+38f;
    #pragma unroll
    for (int i = 0; i < 8; i++) {
        float4 f = *(const float4*)(p + tid * 4 + i * 1024);
        ((float4*)row)[tid + i * 256] = f;
        m = fmaxf(m, fmaxf(fmaxf(f.x, f.y), fmaxf(f.z, f.w)));
    }
    red[tid] = m;
    __syncthreads();
    for (int s = 128; s > 0; s >>= 1) {
        if (tid < s) red[tid] = fmaxf(red[tid], red[tid + s]);
        __syncthreads();
    }
    m = red[0];
    __syncthreads();

    float sum = 0.0f;
    #pragma unroll
    for (int i = 0; i < 8; i++) {
        float4 f = ((float4*)row)[tid + i * 256];
        f.x = expf(f.x - m); f.y = expf(f.y - m);
        f.z = expf(f.z - m); f.w = expf(f.w - m);
        sum += (f.x + f.y) + (f.z + f.w);
        ((float4*)row)[tid + i * 256] = f;
    }
    red[tid] = sum;
    __syncthreads();
    for (int s = 128; s > 0; s >>= 1) {
        if (tid < s) red[tid] += red[tid + s];
        __syncthreads();
    }
    const float inv = 1.0f / red[0];

    #pragma unroll
    for (int i = 0; i < 8; i++) {
        float4 f = ((float4*)row)[tid + i * 256];
        f.x *= inv; f.y *= inv; f.z *= inv; f.w *= inv;
        *(float4*)(p + tid * 4 + i * 1024) = f;
    }
}

// ---------------------------------------------------------------------------
// Launch
// ---------------------------------------------------------------------------
extern "C" void kernel_launch(void* const* d_in, const int* in_sizes, int n_in,
                              void* d_out, int out_size)
{
    const float* x  = (const float*)d_in[0];
    const float* Wq = (const float*)d_in[1];
    const float* Wk = (const float*)d_in[2];
    const float* Wv = (const float*)d_in[3];
    float* out = (float*)d_out;

    float *q, *k, *vt, *sc;
    cudaGetSymbolAddress((void**)&q,  g_q);
    cudaGetSymbolAddress((void**)&k,  g_k);
    cudaGetSymbolAddress((void**)&vt, g_vt);
    cudaGetSymbolAddress((void**)&sc, g_scores);

    cudaFuncSetAttribute(gemm_nt_split,
                         cudaFuncAttributeMaxDynamicSharedMemorySize, SMEM_TOTAL);

    const dim3 blk(256);

    // q = x @ Wq^T, k = x @ Wk^T   [8192,1024]
    {
        dim3 grid(DMODEL / 128, NROWS / 128);   // (8, 64)
        gemm_nt_split<<<grid, blk, SMEM_TOTAL>>>(x, Wq, q, NROWS, DMODEL, DMODEL, 1.0f);
        gemm_nt_split<<<grid, blk, SMEM_TOTAL>>>(x, Wk, k, NROWS, DMODEL, DMODEL, 1.0f);
    }
    // vT = Wv @ x^T   [1024,8192]
    {
        dim3 grid(NROWS / 128, DMODEL / 128);   // (64, 8)
        gemm_nt_split<<<grid, blk, SMEM_TOTAL>>>(Wv, x, vt, DMODEL, NROWS, DMODEL, 1.0f);
    }
    // scores = q @ k^T / 8192   [8192,8192]
    {
        dim3 grid(NROWS / 128, NROWS / 128);    // (64, 64)
        gemm_nt_split<<<grid, blk, SMEM_TOTAL>>>(q, k, sc, NROWS, NROWS, DMODEL,
                                                 1.0f / (float)NROWS);
    }
    // softmax over rows (in place)
    softmax_rows<<<NROWS, 256>>>(sc);

    // out = attn @ v = NT(attn, vT)   [8192,1024]
    {
        dim3 grid(DMODEL / 128, NROWS / 128);   // (8, 64)
        gemm_nt_split<<<grid, blk, SMEM_TOTAL>>>(sc, vt, out, NROWS, DMODEL, NROWS, 1.0f);
    }
}